// round 16
// baseline (speedup 1.0000x reference)
#include <cuda_runtime.h>
#include <cuda_fp16.h>
#include <cstdint>

// Conv2D 3x3 s1 p1 -> FUSED implicit GEMM, mma.sync fp16 m16n8k16, single
// term D = fp16(W)*fp16(x). R16: B staging goes register-free.
//   g_xs[3] = fp16 x with the kw shift PRE-APPLIED (one copy per kw), rows
//   padded W->64 (16B-aligned groups) and H->58 (zero pad rows: kh OOB free).
//   B tile load = 4x cp.async.cg 16B per thread (no LDG staging, no funnel
//   shifts, no predicates) -> ~20 regs freed for the scheduler, LSU ops -60%.
// 3-stage pipeline (2 CTAs/SM), A via cp.async.bulk + mbarrier, one
// __syncthreads per chunk. BK=64 (18 chunks).

namespace {
constexpr int IN_C = 128, OUT_C = 256, H = 56, W = 56, BATCH = 32;
constexpr int HW   = H * W;            // 3136
constexpr int Ndim = BATCH * HW;       // 100352
constexpr int Kdim = IN_C * 9;         // 1152

constexpr int BM = 128, BK = 64;
constexpr int NCH  = Kdim / BK;        // 18 chunks; chunk c: tap r=c>>1, icb=(c&1)*64
constexpr int MBLK = OUT_C / BM;       // 2
constexpr int NT   = Ndim / 128;       // 784

constexpr int HP = 58;                 // padded H (zero rows at 0 and 57)
constexpr int WP = 64;                 // padded W (cols 56..63 zero), 128B rows
constexpr size_t XS_ELEMS = (size_t)BATCH * IN_C * HP * WP;   // 15,204,352

constexpr int A_CH = BM * 144;         // [128 m][64 k] fp16, 144B padded rows = 18432
constexpr int B_CH = BK * 272;         // [64 k][128 n] fp16, 272B padded rows = 17408
constexpr int STAGE  = A_CH + B_CH;    // 35840
constexpr int OFF_A  = 0;
constexpr int OFF_B  = A_CH;
constexpr int NSTG   = 3;
constexpr int SM_BAR = NSTG * STAGE;   // 107520
constexpr int SMEM_TOTAL = SM_BAR + 64;   // 107584 -> 2 CTAs/SM (215KB)

constexpr int XS_ROWS = BATCH * IN_C * HP;             // 237568 rows
constexpr int XS_BLOCKS = (XS_ROWS + 255) / 256;       // 928
}  // namespace

// device scratch (allocation-free rule)
__device__ __align__(16) unsigned char g_A[(size_t)MBLK * NCH * A_CH];  // 0.7MB
__device__ __align__(16) __half g_xs[3 * XS_ELEMS];                     // 91.2MB

// ---------------- helpers ----------------
__device__ __forceinline__ uint32_t smem_u32(const void* p) {
    uint32_t a;
    asm("{ .reg .u64 t; cvta.to.shared.u64 t, %1; cvt.u32.u64 %0, t; }" : "=r"(a) : "l"(p));
    return a;
}
__device__ __forceinline__ void ldsm4(uint32_t r[4], uint32_t addr) {
    asm volatile("ldmatrix.sync.aligned.m8n8.x4.shared.b16 {%0,%1,%2,%3}, [%4];"
                 : "=r"(r[0]), "=r"(r[1]), "=r"(r[2]), "=r"(r[3]) : "r"(addr));
}
__device__ __forceinline__ void ldsm4t(uint32_t* r, uint32_t addr) {
    asm volatile("ldmatrix.sync.aligned.m8n8.x4.trans.shared.b16 {%0,%1,%2,%3}, [%4];"
                 : "=r"(r[0]), "=r"(r[1]), "=r"(r[2]), "=r"(r[3]) : "r"(addr));
}
__device__ __forceinline__ void mma_fp16(float acc[4], const uint32_t a[4],
                                         uint32_t b0, uint32_t b1) {
    asm volatile(
        "mma.sync.aligned.m16n8k16.row.col.f32.f16.f16.f32 "
        "{%0,%1,%2,%3}, {%4,%5,%6,%7}, {%8,%9}, {%0,%1,%2,%3};"
        : "+f"(acc[0]), "+f"(acc[1]), "+f"(acc[2]), "+f"(acc[3])
        : "r"(a[0]), "r"(a[1]), "r"(a[2]), "r"(a[3]), "r"(b0), "r"(b1));
}
__device__ __forceinline__ uint32_t pack2h(__half a, __half b) {
    __half2 t(a, b);
    return *reinterpret_cast<uint32_t*>(&t);
}
#define MBAR_INIT(a, n)   asm volatile("mbarrier.init.shared.b64 [%0], %1;" :: "r"(a), "r"(n) : "memory")
#define MBAR_EXPECT(a, b) asm volatile("mbarrier.arrive.expect_tx.shared.b64 _, [%0], %1;" :: "r"(a), "r"(b) : "memory")
#define MBAR_INVAL(a)     asm volatile("mbarrier.inval.shared.b64 [%0];" :: "r"(a) : "memory")
__device__ __forceinline__ void mbar_wait(uint32_t mbar, uint32_t parity) {
    asm volatile(
        "{\n\t.reg .pred P;\n"
        "WL_%=:\n\t"
        "mbarrier.try_wait.parity.acquire.cta.shared::cta.b64 P, [%0], %1, 0x989680;\n\t"
        "@P bra.uni WD_%=;\n\t"
        "bra.uni WL_%=;\n"
        "WD_%=:\n\t}"
        :: "r"(mbar), "r"(parity) : "memory");
}
__device__ __forceinline__ void bulk_g2s(uint32_t dst, const void* src, uint32_t bytes, uint32_t mbar) {
    asm volatile(
        "cp.async.bulk.shared::cluster.global.mbarrier::complete_tx::bytes [%0], [%1], %2, [%3];"
        :: "r"(dst), "l"(src), "r"(bytes), "r"(mbar) : "memory");
}
__device__ __forceinline__ void cp16(uint32_t dst, const void* src) {
    asm volatile("cp.async.cg.shared.global [%0], [%1], 16;" :: "r"(dst), "l"(src) : "memory");
}
#define CP_COMMIT() asm volatile("cp.async.commit_group;" ::: "memory")
#define CP_WAIT1()  asm volatile("cp.async.wait_group 1;" ::: "memory")

// ---------------- prep: shifted/padded fp16 x copies + weight images -------
__global__ __launch_bounds__(256)
void prep_all(const float* __restrict__ x, const float* __restrict__ Wk) {
    if (blockIdx.x < XS_BLOCKS) {
        const int idx = blockIdx.x * 256 + threadIdx.x;   // one dst row
        if (idx >= XS_ROWS) return;
        const int hr  = idx % HP;          // 0..57 (padded row)
        const int icn = idx / HP;          // ni*IN_C + ic
        __half* d0 = g_xs + 0 * XS_ELEMS + (size_t)idx * WP;
        __half* d1 = g_xs + 1 * XS_ELEMS + (size_t)idx * WP;
        __half* d2 = g_xs + 2 * XS_ELEMS + (size_t)idx * WP;

        if (hr == 0 || hr == HP - 1) {     // zero pad rows
            const uint4 z = make_uint4(0, 0, 0, 0);
            #pragma unroll
            for (int i = 0; i < 8; ++i) {
                reinterpret_cast<uint4*>(d0)[i] = z;
                reinterpret_cast<uint4*>(d1)[i] = z;
                reinterpret_cast<uint4*>(d2)[i] = z;
            }
            return;
        }
        const float* src = x + ((size_t)icn * H + (hr - 1)) * W;
        uint32_t h2[28];                   // 56 halfs as 28 half2 words
        #pragma unroll
        for (int i = 0; i < 14; ++i) {
            float4 v = __ldg(reinterpret_cast<const float4*>(src) + i);
            h2[2 * i]     = pack2h(__float2half(v.x), __float2half(v.y));
            h2[2 * i + 1] = pack2h(__float2half(v.z), __float2half(v.w));
        }
        uint32_t* o0 = reinterpret_cast<uint32_t*>(d0);   // kw=0: y[w]=x[w-1]
        uint32_t* o1 = reinterpret_cast<uint32_t*>(d1);   // kw=1: y[w]=x[w]
        uint32_t* o2 = reinterpret_cast<uint32_t*>(d2);   // kw=2: y[w]=x[w+1]
        #pragma unroll
        for (int i = 0; i < 28; ++i) {
            uint32_t prev = (i > 0)  ? h2[i - 1] : 0u;
            uint32_t next = (i < 27) ? h2[i + 1] : 0u;
            o0[i] = __funnelshift_r(prev, h2[i], 16);
            o1[i] = h2[i];
            o2[i] = __funnelshift_r(h2[i], next, 16);
        }
        #pragma unroll
        for (int i = 28; i < 32; ++i) { o0[i] = 0; o1[i] = 0; o2[i] = 0; }  // col pad
        return;
    }
    // ---- weights -> k-reordered SMEM-image fp16 (BK=64, 144B rows) ----
    const int c = blockIdx.x - XS_BLOCKS;          // 18 chunks
    const int m = threadIdx.x;                     // 256 = OUT_C
    const int r  = c >> 1;                         // spatial tap 0..8
    const int icb = (c & 1) * 64;

    const float* src = Wk + (size_t)m * Kdim + r;  // orig k = ic*9 + r
    size_t base = ((size_t)(m >> 7) * NCH + c) * A_CH + (size_t)(m & 127) * 144;
    #pragma unroll
    for (int kkg = 0; kkg < 8; ++kkg) {
        uint32_t hv[4];
        #pragma unroll
        for (int p = 0; p < 4; ++p) {
            int ic0 = icb + kkg * 8 + 2 * p;
            hv[p] = pack2h(__float2half(src[ic0 * 9]),
                           __float2half(src[(ic0 + 1) * 9]));
        }
        *reinterpret_cast<uint4*>(g_A + base + kkg * 16) =
            make_uint4(hv[0], hv[1], hv[2], hv[3]);
    }
}

// ---------------- fused GEMM: cp.async B, bulk A, 3 stages -----------------
__global__ __launch_bounds__(256, 2)
void conv_fused6(const float* __restrict__ bias, float* __restrict__ out)
{
    extern __shared__ char smem[];
    const uint32_t sb = smem_u32(smem);
    const int tid = threadIdx.x, lane = tid & 31, wp = tid >> 5;
    const int warp_m = wp >> 2, warp_n = wp & 3;   // 2m x 4n, 64x32 warp tile
    const int mblk = blockIdx.x, t = blockIdx.y;

    // ---- gather geometry: thread = n-group g (8 cols), 4 rows r0+{0,16,32,48} ----
    const int r0 = tid >> 4;                       // 0..15
    const int g  = tid & 15;
    const int n0  = t * 128 + g * 8;
    const int ni  = n0 / HW;
    const int hw0 = n0 - ni * HW;
    const int oh  = hw0 / W;
    const int ow0 = hw0 - oh * W;                  // multiple of 8

    const unsigned char* gA = g_A + (size_t)mblk * NCH * A_CH;

    uint32_t full[NSTG];
    #pragma unroll
    for (int s = 0; s < NSTG; ++s) full[s] = sb + SM_BAR + s * 8;
    if (tid == 0) {
        #pragma unroll
        for (int s = 0; s < NSTG; ++s) MBAR_INIT(full[s], 1);
    }
    __syncthreads();

    auto loadA = [&](int c, int s) {
        MBAR_EXPECT(full[s], A_CH);
        bulk_g2s(sb + s * STAGE + OFF_A, gA + (size_t)c * A_CH, A_CH, full[s]);
    };

    // B: pure aligned copy from the pre-shifted/padded x image
    auto cpB = [&](int c, int s) {
        const int r   = c >> 1;
        const int kh  = r / 3, kwv = r - kh * 3;
        const int icb = (c & 1) * 64;
        const __half* base = g_xs + (size_t)kwv * XS_ELEMS +
            ((size_t)(ni * IN_C + icb) * HP + (oh + kh)) * WP + ow0;
        const uint32_t dst0 = sb + s * STAGE + OFF_B + g * 16;
        #pragma unroll
        for (int u = 0; u < 4; ++u) {
            const int row = r0 + u * 16;
            cp16(dst0 + row * 272, base + (size_t)row * HP * WP);
        }
    };

    // prologue: stages 0,1 in flight
    cpB(0, 0); CP_COMMIT();
    cpB(1, 1); CP_COMMIT();
    if (tid == 0) { loadA(0, 0); loadA(1, 1); }

    float acc[4][4][4];
    #pragma unroll
    for (int a = 0; a < 4; ++a)
        #pragma unroll
        for (int b = 0; b < 4; ++b)
            #pragma unroll
            for (int cc = 0; cc < 4; ++cc) acc[a][b][cc] = 0.f;

    const uint32_t a_lane = (warp_m * 64 + (lane & 15)) * 144 + (lane >> 4) * 16;
    const uint32_t b_lane = (lane & 15) * 272 + warp_n * 64 + (lane >> 4) * 16;

    auto compute = [&](int buf) {
        const uint32_t ab = sb + buf * STAGE + OFF_A + a_lane;
        const uint32_t bb = sb + buf * STAGE + OFF_B + b_lane;
        #pragma unroll
        for (int ks = 0; ks < 4; ++ks) {
            uint32_t Bv[2][4];
            #pragma unroll
            for (int jh = 0; jh < 2; ++jh)
                ldsm4t(Bv[jh], bb + ks * 4352 + jh * 32);
            #pragma unroll
            for (int mt = 0; mt < 4; ++mt) {
                uint32_t Av[4];
                ldsm4(Av, ab + mt * 2304 + ks * 32);
                #pragma unroll
                for (int nt = 0; nt < 4; ++nt) {
                    uint32_t b0 = Bv[nt >> 1][(nt & 1) * 2];
                    uint32_t b1 = Bv[nt >> 1][(nt & 1) * 2 + 1];
                    mma_fp16(acc[mt][nt], Av, b0, b1);
                }
            }
        }
    };

    // ---- mainloop: 18 iterations, ONE syncthreads each ----
    int fp3[NSTG] = {0, 0, 0};
    for (int c = 0; c < NCH; ++c) {
        const int s = c % NSTG;
        CP_WAIT1();                        // own B(c) copies complete
        mbar_wait(full[s], fp3[s]); fp3[s] ^= 1;   // A(c) complete
        __syncthreads();                   // all threads' B(c)/compute(c-1) done
        if (c + 2 < NCH) {                 // stage (c+2)%3 == (c-1)%3: free now
            cpB(c + 2, (c + 2) % NSTG);
            if (tid == 0) loadA(c + 2, (c + 2) % NSTG);
        }
        CP_COMMIT();                       // always: keeps group numbering fixed
        compute(s);
    }

    // ---- epilogue: bias + direct stores (layout proven since R3) ----
    #pragma unroll
    for (int mt = 0; mt < 4; ++mt) {
        int oc0 = mblk * BM + warp_m * 64 + mt * 16 + (lane >> 2);
        float b0 = bias[oc0], b1 = bias[oc0 + 8];
        #pragma unroll
        for (int nt = 0; nt < 4; ++nt) {
            int gg = t * 128 + warp_n * 32 + nt * 8 + (lane & 3) * 2;
            int nim = gg / HW;
            int hw  = gg - nim * HW;
            float2 v0 = make_float2(acc[mt][nt][0] + b0, acc[mt][nt][1] + b0);
            float2 v1 = make_float2(acc[mt][nt][2] + b1, acc[mt][nt][3] + b1);
            *reinterpret_cast<float2*>(out + ((size_t)nim * OUT_C + oc0) * HW + hw)     = v0;
            *reinterpret_cast<float2*>(out + ((size_t)nim * OUT_C + oc0 + 8) * HW + hw) = v1;
        }
    }

    __syncthreads();
    if (tid == 0) {
        #pragma unroll
        for (int s = 0; s < NSTG; ++s) MBAR_INVAL(full[s]);
    }
}

// ---------------- launch ----------------
extern "C" void kernel_launch(void* const* d_in, const int* in_sizes, int n_in,
                              void* d_out, int out_size) {
    const float* x    = (const float*)d_in[0];
    const float* Wk   = (const float*)d_in[1];
    const float* bias = (const float*)d_in[2];
    float* out        = (float*)d_out;

    cudaFuncSetAttribute(conv_fused6, cudaFuncAttributeMaxDynamicSharedMemorySize, SMEM_TOTAL);

    prep_all<<<XS_BLOCKS + NCH, 256>>>(x, Wk);
    conv_fused6<<<dim3(MBLK, NT), 256, SMEM_TOTAL>>>(bias, out);
}

// round 17
// speedup vs baseline: 1.4460x; 1.4460x over previous
#include <cuda_runtime.h>
#include <cuda_fp16.h>
#include <cstdint>

// Conv2D 3x3 s1 p1 -> FUSED implicit GEMM, mma.sync fp16 m16n8k16, single
// term D = fp16(W)*fp16(x). R17 = R16 GEMM (192.6us, tensor 51%) UNCHANGED +
// prep rewritten for coalesced stores: one thread per (row, 8-col group), so
// adjacent lanes write adjacent 16B (3x STG.128 coalesced) instead of R16's
// 84 scalar strided STG.32 per thread (which cost ~155us of prep time).

namespace {
constexpr int IN_C = 128, OUT_C = 256, H = 56, W = 56, BATCH = 32;
constexpr int HW   = H * W;            // 3136
constexpr int Ndim = BATCH * HW;       // 100352
constexpr int Kdim = IN_C * 9;         // 1152

constexpr int BM = 128, BK = 64;
constexpr int NCH  = Kdim / BK;        // 18 chunks; chunk c: tap r=c>>1, icb=(c&1)*64
constexpr int MBLK = OUT_C / BM;       // 2
constexpr int NT   = Ndim / 128;       // 784

constexpr int HP = 58;                 // padded H (zero rows at 0 and 57)
constexpr int WP = 64;                 // padded W (cols 56..63 zero), 128B rows
constexpr size_t XS_ELEMS = (size_t)BATCH * IN_C * HP * WP;   // 15,204,352

constexpr int A_CH = BM * 144;         // [128 m][64 k] fp16, 144B padded rows = 18432
constexpr int B_CH = BK * 272;         // [64 k][128 n] fp16, 272B padded rows = 17408
constexpr int STAGE  = A_CH + B_CH;    // 35840
constexpr int OFF_A  = 0;
constexpr int OFF_B  = A_CH;
constexpr int NSTG   = 3;
constexpr int SM_BAR = NSTG * STAGE;   // 107520
constexpr int SMEM_TOTAL = SM_BAR + 64;   // 107584 -> 2 CTAs/SM (215KB)

constexpr int XS_ROWS   = BATCH * IN_C * HP;              // 237568 rows
constexpr int XS_GROUPS = XS_ROWS * 8;                    // 1,900,544 threads
constexpr int XS_BLOCKS = (XS_GROUPS + 255) / 256;        // 7424
}  // namespace

// device scratch (allocation-free rule)
__device__ __align__(16) unsigned char g_A[(size_t)MBLK * NCH * A_CH];  // 0.7MB
__device__ __align__(16) __half g_xs[3 * XS_ELEMS];                     // 91.2MB

// ---------------- helpers ----------------
__device__ __forceinline__ uint32_t smem_u32(const void* p) {
    uint32_t a;
    asm("{ .reg .u64 t; cvta.to.shared.u64 t, %1; cvt.u32.u64 %0, t; }" : "=r"(a) : "l"(p));
    return a;
}
__device__ __forceinline__ void ldsm4(uint32_t r[4], uint32_t addr) {
    asm volatile("ldmatrix.sync.aligned.m8n8.x4.shared.b16 {%0,%1,%2,%3}, [%4];"
                 : "=r"(r[0]), "=r"(r[1]), "=r"(r[2]), "=r"(r[3]) : "r"(addr));
}
__device__ __forceinline__ void ldsm4t(uint32_t* r, uint32_t addr) {
    asm volatile("ldmatrix.sync.aligned.m8n8.x4.trans.shared.b16 {%0,%1,%2,%3}, [%4];"
                 : "=r"(r[0]), "=r"(r[1]), "=r"(r[2]), "=r"(r[3]) : "r"(addr));
}
__device__ __forceinline__ void mma_fp16(float acc[4], const uint32_t a[4],
                                         uint32_t b0, uint32_t b1) {
    asm volatile(
        "mma.sync.aligned.m16n8k16.row.col.f32.f16.f16.f32 "
        "{%0,%1,%2,%3}, {%4,%5,%6,%7}, {%8,%9}, {%0,%1,%2,%3};"
        : "+f"(acc[0]), "+f"(acc[1]), "+f"(acc[2]), "+f"(acc[3])
        : "r"(a[0]), "r"(a[1]), "r"(a[2]), "r"(a[3]), "r"(b0), "r"(b1));
}
__device__ __forceinline__ uint32_t pack2h(__half a, __half b) {
    __half2 t(a, b);
    return *reinterpret_cast<uint32_t*>(&t);
}
#define MBAR_INIT(a, n)   asm volatile("mbarrier.init.shared.b64 [%0], %1;" :: "r"(a), "r"(n) : "memory")
#define MBAR_EXPECT(a, b) asm volatile("mbarrier.arrive.expect_tx.shared.b64 _, [%0], %1;" :: "r"(a), "r"(b) : "memory")
#define MBAR_INVAL(a)     asm volatile("mbarrier.inval.shared.b64 [%0];" :: "r"(a) : "memory")
__device__ __forceinline__ void mbar_wait(uint32_t mbar, uint32_t parity) {
    asm volatile(
        "{\n\t.reg .pred P;\n"
        "WL_%=:\n\t"
        "mbarrier.try_wait.parity.acquire.cta.shared::cta.b64 P, [%0], %1, 0x989680;\n\t"
        "@P bra.uni WD_%=;\n\t"
        "bra.uni WL_%=;\n"
        "WD_%=:\n\t}"
        :: "r"(mbar), "r"(parity) : "memory");
}
__device__ __forceinline__ void bulk_g2s(uint32_t dst, const void* src, uint32_t bytes, uint32_t mbar) {
    asm volatile(
        "cp.async.bulk.shared::cluster.global.mbarrier::complete_tx::bytes [%0], [%1], %2, [%3];"
        :: "r"(dst), "l"(src), "r"(bytes), "r"(mbar) : "memory");
}
__device__ __forceinline__ void cp16(uint32_t dst, const void* src) {
    asm volatile("cp.async.cg.shared.global [%0], [%1], 16;" :: "r"(dst), "l"(src) : "memory");
}
#define CP_COMMIT() asm volatile("cp.async.commit_group;" ::: "memory")
#define CP_WAIT1()  asm volatile("cp.async.wait_group 1;" ::: "memory")

// ---------------- prep: coalesced shifted/padded fp16 x + weight images ----
__global__ __launch_bounds__(256)
void prep_all(const float* __restrict__ x, const float* __restrict__ Wk) {
    if (blockIdx.x < XS_BLOCKS) {
        const int gidx = blockIdx.x * 256 + threadIdx.x;
        if (gidx >= XS_GROUPS) return;
        const int j   = gidx & 7;            // 8-col group within padded row
        const int row = gidx >> 3;           // padded row id
        const int hr  = row % HP;
        const int icn = row / HP;
        const size_t doff = (size_t)row * WP + j * 8;
        uint4* d0 = reinterpret_cast<uint4*>(g_xs + 0 * XS_ELEMS + doff);
        uint4* d1 = reinterpret_cast<uint4*>(g_xs + 1 * XS_ELEMS + doff);
        uint4* d2 = reinterpret_cast<uint4*>(g_xs + 2 * XS_ELEMS + doff);

        if (hr == 0 || hr == HP - 1 || j == 7) {   // pad rows / pad cols
            const uint4 z = make_uint4(0, 0, 0, 0);
            *d0 = z; *d1 = z; *d2 = z;
            return;
        }
        const float* src = x + ((size_t)icn * H + (hr - 1)) * W + j * 8;
        float4 v0 = __ldg(reinterpret_cast<const float4*>(src));
        float4 v1 = __ldg(reinterpret_cast<const float4*>(src) + 1);
        __half lft = (j > 0) ? __float2half(__ldg(src - 1)) : __half(0.f);
        __half rgt = (j < 6) ? __float2half(__ldg(src + 8)) : __half(0.f);

        uint32_t h2[4];
        h2[0] = pack2h(__float2half(v0.x), __float2half(v0.y));
        h2[1] = pack2h(__float2half(v0.z), __float2half(v0.w));
        h2[2] = pack2h(__float2half(v1.x), __float2half(v1.y));
        h2[3] = pack2h(__float2half(v1.z), __float2half(v1.w));
        uint32_t lw = pack2h(__half(0.f), lft);    // x[-1] in high half
        uint32_t rw = pack2h(rgt, __half(0.f));    // x[+8] in low half

        uint4 o0, o1, o2;
        o1 = make_uint4(h2[0], h2[1], h2[2], h2[3]);
        o0.x = __funnelshift_r(lw,    h2[0], 16);  // y[w] = x[w-1]
        o0.y = __funnelshift_r(h2[0], h2[1], 16);
        o0.z = __funnelshift_r(h2[1], h2[2], 16);
        o0.w = __funnelshift_r(h2[2], h2[3], 16);
        o2.x = __funnelshift_r(h2[0], h2[1], 16);  // y[w] = x[w+1]... careful
        // o2[i] = {x[2i+1], x[2i+2]}: shift left by one half
        o2.x = __funnelshift_r(h2[0], h2[1], 16);
        o2.y = __funnelshift_r(h2[1], h2[2], 16);
        o2.z = __funnelshift_r(h2[2], h2[3], 16);
        o2.w = __funnelshift_r(h2[3], rw,    16);
        // NOTE: o2.x..z equal shifted pairs {x1,x2},{x3,x4},{x5,x6} -- correct;
        // o0.y..w equal {x1,x2}? No: funnelshift_r(lo,hi,16) = {lo.hi, hi.lo}
        //   o0.y = {h2[0].hi, h2[1].lo} = {x1, x2}?? x words: h2[i]={x[2i],x[2i+1]}
        //   {h2[0].hi=x1, h2[1].lo=x2} -> o0.y = {x1,x2} = y[2],y[3] where
        //   y[w]=x[w-1] -> y[2]=x[1], y[3]=x[2]. Correct.
        //   o2.x = {h2[0].hi=x1, h2[1].lo=x2} -> y[0]=x[1], y[1]=x[2]. Correct.
        *d0 = o0; *d1 = o1; *d2 = o2;
        return;
    }
    // ---- weights -> k-reordered SMEM-image fp16 (BK=64, 144B rows) ----
    const int c = blockIdx.x - XS_BLOCKS;          // 18 chunks
    const int m = threadIdx.x;                     // 256 = OUT_C
    const int r  = c >> 1;                         // spatial tap 0..8
    const int icb = (c & 1) * 64;

    const float* src = Wk + (size_t)m * Kdim + r;  // orig k = ic*9 + r
    size_t base = ((size_t)(m >> 7) * NCH + c) * A_CH + (size_t)(m & 127) * 144;
    #pragma unroll
    for (int kkg = 0; kkg < 8; ++kkg) {
        uint32_t hv[4];
        #pragma unroll
        for (int p = 0; p < 4; ++p) {
            int ic0 = icb + kkg * 8 + 2 * p;
            hv[p] = pack2h(__float2half(src[ic0 * 9]),
                           __float2half(src[(ic0 + 1) * 9]));
        }
        *reinterpret_cast<uint4*>(g_A + base + kkg * 16) =
            make_uint4(hv[0], hv[1], hv[2], hv[3]);
    }
}

// ---------------- fused GEMM: cp.async B, bulk A, 3 stages (R16-proven) ----
__global__ __launch_bounds__(256, 2)
void conv_fused6(const float* __restrict__ bias, float* __restrict__ out)
{
    extern __shared__ char smem[];
    const uint32_t sb = smem_u32(smem);
    const int tid = threadIdx.x, lane = tid & 31, wp = tid >> 5;
    const int warp_m = wp >> 2, warp_n = wp & 3;   // 2m x 4n, 64x32 warp tile
    const int mblk = blockIdx.x, t = blockIdx.y;

    const int r0 = tid >> 4;                       // 0..15
    const int g  = tid & 15;
    const int n0  = t * 128 + g * 8;
    const int ni  = n0 / HW;
    const int hw0 = n0 - ni * HW;
    const int oh  = hw0 / W;
    const int ow0 = hw0 - oh * W;                  // multiple of 8

    const unsigned char* gA = g_A + (size_t)mblk * NCH * A_CH;

    uint32_t full[NSTG];
    #pragma unroll
    for (int s = 0; s < NSTG; ++s) full[s] = sb + SM_BAR + s * 8;
    if (tid == 0) {
        #pragma unroll
        for (int s = 0; s < NSTG; ++s) MBAR_INIT(full[s], 1);
    }
    __syncthreads();

    auto loadA = [&](int c, int s) {
        MBAR_EXPECT(full[s], A_CH);
        bulk_g2s(sb + s * STAGE + OFF_A, gA + (size_t)c * A_CH, A_CH, full[s]);
    };

    auto cpB = [&](int c, int s) {
        const int r   = c >> 1;
        const int kh  = r / 3, kwv = r - kh * 3;
        const int icb = (c & 1) * 64;
        const __half* base = g_xs + (size_t)kwv * XS_ELEMS +
            ((size_t)(ni * IN_C + icb) * HP + (oh + kh)) * WP + ow0;
        const uint32_t dst0 = sb + s * STAGE + OFF_B + g * 16;
        #pragma unroll
        for (int u = 0; u < 4; ++u) {
            const int row = r0 + u * 16;
            cp16(dst0 + row * 272, base + (size_t)row * HP * WP);
        }
    };

    cpB(0, 0); CP_COMMIT();
    cpB(1, 1); CP_COMMIT();
    if (tid == 0) { loadA(0, 0); loadA(1, 1); }

    float acc[4][4][4];
    #pragma unroll
    for (int a = 0; a < 4; ++a)
        #pragma unroll
        for (int b = 0; b < 4; ++b)
            #pragma unroll
            for (int cc = 0; cc < 4; ++cc) acc[a][b][cc] = 0.f;

    const uint32_t a_lane = (warp_m * 64 + (lane & 15)) * 144 + (lane >> 4) * 16;
    const uint32_t b_lane = (lane & 15) * 272 + warp_n * 64 + (lane >> 4) * 16;

    auto compute = [&](int buf) {
        const uint32_t ab = sb + buf * STAGE + OFF_A + a_lane;
        const uint32_t bb = sb + buf * STAGE + OFF_B + b_lane;
        #pragma unroll
        for (int ks = 0; ks < 4; ++ks) {
            uint32_t Bv[2][4];
            #pragma unroll
            for (int jh = 0; jh < 2; ++jh)
                ldsm4t(Bv[jh], bb + ks * 4352 + jh * 32);
            #pragma unroll
            for (int mt = 0; mt < 4; ++mt) {
                uint32_t Av[4];
                ldsm4(Av, ab + mt * 2304 + ks * 32);
                #pragma unroll
                for (int nt = 0; nt < 4; ++nt) {
                    uint32_t b0 = Bv[nt >> 1][(nt & 1) * 2];
                    uint32_t b1 = Bv[nt >> 1][(nt & 1) * 2 + 1];
                    mma_fp16(acc[mt][nt], Av, b0, b1);
                }
            }
        }
    };

    int fp3[NSTG] = {0, 0, 0};
    for (int c = 0; c < NCH; ++c) {
        const int s = c % NSTG;
        CP_WAIT1();
        mbar_wait(full[s], fp3[s]); fp3[s] ^= 1;
        __syncthreads();
        if (c + 2 < NCH) {
            cpB(c + 2, (c + 2) % NSTG);
            if (tid == 0) loadA(c + 2, (c + 2) % NSTG);
        }
        CP_COMMIT();
        compute(s);
    }

    #pragma unroll
    for (int mt = 0; mt < 4; ++mt) {
        int oc0 = mblk * BM + warp_m * 64 + mt * 16 + (lane >> 2);
        float b0 = bias[oc0], b1 = bias[oc0 + 8];
        #pragma unroll
        for (int nt = 0; nt < 4; ++nt) {
            int gg = t * 128 + warp_n * 32 + nt * 8 + (lane & 3) * 2;
            int nim = gg / HW;
            int hw  = gg - nim * HW;
            float2 v0 = make_float2(acc[mt][nt][0] + b0, acc[mt][nt][1] + b0);
            float2 v1 = make_float2(acc[mt][nt][2] + b1, acc[mt][nt][3] + b1);
            *reinterpret_cast<float2*>(out + ((size_t)nim * OUT_C + oc0) * HW + hw)     = v0;
            *reinterpret_cast<float2*>(out + ((size_t)nim * OUT_C + oc0 + 8) * HW + hw) = v1;
        }
    }

    __syncthreads();
    if (tid == 0) {
        #pragma unroll
        for (int s = 0; s < NSTG; ++s) MBAR_INVAL(full[s]);
    }
}

// ---------------- launch ----------------
extern "C" void kernel_launch(void* const* d_in, const int* in_sizes, int n_in,
                              void* d_out, int out_size) {
    const float* x    = (const float*)d_in[0];
    const float* Wk   = (const float*)d_in[1];
    const float* bias = (const float*)d_in[2];
    float* out        = (float*)d_out;

    cudaFuncSetAttribute(conv_fused6, cudaFuncAttributeMaxDynamicSharedMemorySize, SMEM_TOTAL);

    prep_all<<<XS_BLOCKS + NCH, 256>>>(x, Wk);
    conv_fused6<<<dim3(MBLK, NT), 256, SMEM_TOTAL>>>(bias, out);
}